// round 15
// baseline (speedup 1.0000x reference)
#include <cuda_runtime.h>
#include <cstdint>
#include <math.h>

#define ND 4096
#define BM 64
#define BN 128
#define BK 32
#define NT (ND / BK)          // 128 k-tiles; splitK=2 fold after tiles 63,127

#define A_PITCH_B 272         // bytes per A row (68 floats)
#define A_BYTES   26112       // 3 planes * 32 rows * 272
#define B_PITCH_B 1056        // bytes per B row (264 floats: 256 data + pad)
#define STG_BYTES (A_BYTES + 32 * B_PITCH_B)   // 59904
#define SMEM_BYTES (3 * STG_BYTES)             // 179712

// Scratch (allocation-free): transposed A planes + duplicated W.
static __device__ float g_rT[(size_t)ND * ND];
static __device__ float g_lowT[(size_t)ND * ND];
static __device__ float g_highT[(size_t)ND * ND];
static __device__ float g_Wd[2 * (size_t)ND * ND];   // [k][2n], elements doubled

// f32x2 packed helpers (per-lane IEEE RN — bit-identical to scalar FFMA/FADD)
#define FMA2(acc, a, b) asm("fma.rn.f32x2 %0, %1, %2, %0;" : "+l"(acc) : "l"(a), "l"(b))
#define ADD2(acc, v)    asm("add.rn.f32x2 %0, %0, %1;" : "+l"(acc) : "l"(v))
#define UNPK(lo, hi, v) asm("mov.b64 {%0, %1}, %2;" : "=f"(lo), "=f"(hi) : "l"(v))

#define CP16(dst, src) \
    asm volatile("cp.async.cg.shared.global [%0], [%1], 16;" :: "r"(dst), "l"(src))

// 16B-granular XOR swizzle killing the 2-way conflict of 32B-strided rows
#define BSWZ(o) ((o) ^ ((((o) >> 7) & 1) << 4))

__device__ __forceinline__ uint32_t smem_u32(const void* p) {
    uint32_t a;
    asm("{ .reg .u64 t; cvta.to.shared.u64 t, %1; cvt.u32.u64 %0, t; }" : "=r"(a) : "l"(p));
    return a;
}

// Digit split (exact jnp semantics, bit-exact since R10) + 32x32 transpose.
__global__ void __launch_bounds__(256) prep_T(const float* __restrict__ x,
                                              const float* __restrict__ r) {
    __shared__ float tR[32][33], tL[32][33], tH[32][33];
    const int tx = threadIdx.x & 31, ty = threadIdx.x >> 5;
    const int m0 = blockIdx.x * 32, k0 = blockIdx.y * 32;
#pragma unroll
    for (int i = 0; i < 4; ++i) {
        const int ml = ty + 8 * i;
        const size_t idx = (size_t)(m0 + ml) * ND + k0 + tx;
        float rv = r[idx];
        float xb = __fadd_rn(x[idx], rv);
        float low = fmodf(xb, 2291.0f);
        if (low < 0.0f) low = __fadd_rn(low, 2291.0f);
        float high = rintf(__fdiv_rn(__fsub_rn(xb, low), 2291.0f));
        tR[ml][tx] = rv;
        tL[ml][tx] = low;
        tH[ml][tx] = high;
    }
    __syncthreads();
#pragma unroll
    for (int i = 0; i < 4; ++i) {
        const int kl = ty + 8 * i;
        const size_t o = (size_t)(k0 + kl) * ND + m0 + tx;
        g_rT[o]    = tR[tx][kl];
        g_lowT[o]  = tL[tx][kl];
        g_highT[o] = tH[tx][kl];
    }
}

// Duplicate W elementwise: g_Wd[k][2n] = g_Wd[k][2n+1] = W[k][n].
__global__ void __launch_bounds__(256) prep_Wd(const float* __restrict__ W) {
    size_t i = (size_t)blockIdx.x * 256 + threadIdx.x;   // float4 index
    float4 w = ((const float4*)W)[i];
    float4* dst = (float4*)g_Wd + 2 * i;
    dst[0] = make_float4(w.x, w.x, w.y, w.y);
    dst[1] = make_float4(w.z, w.z, w.w, w.w);
}

// Fused triple-SGEMM, splitK=2 rounding (bit-exact), f32x2 math,
// 3-stage cp.async pipeline (race-free R14 ordering), pre-duplicated B
// (zero packing movs in the inner loop).
__global__ void __launch_bounds__(256) gemm3_dup_kernel(
        const float* __restrict__ bvec,
        float* __restrict__ out) {
    extern __shared__ __align__(16) char smem[];

    const int tid  = threadIdx.x;
    const int tx   = tid & 15;
    const int ty   = tid >> 4;
    const int row0 = blockIdx.y * BM;
    const int col0 = blockIdx.x * BN;

    const uint32_t sbase = smem_u32(smem);
    const float* srcA[3] = {g_rT, g_lowT, g_highT};

    // B fragment byte offsets within a k-row (swizzled, 16B chunks)
    const uint32_t bo0 = BSWZ((uint32_t)(32 * tx));
    const uint32_t bo1 = BSWZ((uint32_t)(32 * tx + 16));
    const uint32_t bo2 = BSWZ((uint32_t)(512 + 32 * tx));
    const uint32_t bo3 = BSWZ((uint32_t)(512 + 32 * tx + 16));

    uint64_t acc[3][2][8], run[3][2][8];
#pragma unroll
    for (int m = 0; m < 3; ++m)
#pragma unroll
        for (int p = 0; p < 2; ++p)
#pragma unroll
            for (int n = 0; n < 8; ++n) { acc[m][p][n] = 0ull; run[m][p][n] = 0ull; }

    // Loader: A = 1536 chunks (6/thread), B = 2048 chunks (8/thread)
#define LOAD_TILE(t, stg)                                                          \
    do {                                                                           \
        const int _k0 = (t) * BK;                                                  \
        const uint32_t _sb = sbase + (uint32_t)(stg) * STG_BYTES;                  \
        _Pragma("unroll")                                                          \
        for (int _i = 0; _i < 6; ++_i) {                                           \
            const int _lin = _i * 256 + tid;                                       \
            const int _pl = _lin >> 9, _kr = (_lin >> 4) & 31, _q = _lin & 15;     \
            const float* _s = srcA[_pl] + (size_t)(_k0 + _kr) * ND + row0 + _q * 4;\
            CP16(_sb + (uint32_t)((_pl * 32 + _kr) * A_PITCH_B + _q * 16), _s);    \
        }                                                                          \
        _Pragma("unroll")                                                          \
        for (int _i = 0; _i < 8; ++_i) {                                           \
            const int _lin = _i * 256 + tid;                                       \
            const int _kr = _lin >> 6, _q = _lin & 63;                             \
            const float* _s = g_Wd + (size_t)(_k0 + _kr) * (2 * ND) + 2 * col0 + _q * 4; \
            CP16(_sb + (uint32_t)(A_BYTES + _kr * B_PITCH_B + BSWZ(_q * 16)), _s); \
        }                                                                          \
    } while (0)

    LOAD_TILE(0, 0);
    asm volatile("cp.async.commit_group;" ::: "memory");
    LOAD_TILE(1, 1);
    asm volatile("cp.async.commit_group;" ::: "memory");

    int stage = 0;
    for (int t = 0; t < NT; ++t) {
        asm volatile("cp.async.wait_group 1;" ::: "memory");
        __syncthreads();
        if (t + 2 < NT) LOAD_TILE(t + 2, (stage + 2) % 3);
        asm volatile("cp.async.commit_group;" ::: "memory");

        const char* As = smem + stage * STG_BYTES;
        const char* Bs = As + A_BYTES;

#pragma unroll
        for (int k = 0; k < BK; ++k) {
            ulonglong2 aR = *(const ulonglong2*)(As + (0 * 32 + k) * A_PITCH_B + (ty << 4));
            ulonglong2 aL = *(const ulonglong2*)(As + (1 * 32 + k) * A_PITCH_B + (ty << 4));
            ulonglong2 aH = *(const ulonglong2*)(As + (2 * 32 + k) * A_PITCH_B + (ty << 4));
            const char* Bk = Bs + k * B_PITCH_B;
            ulonglong2 b01 = *(const ulonglong2*)(Bk + bo0);
            ulonglong2 b23 = *(const ulonglong2*)(Bk + bo1);
            ulonglong2 b45 = *(const ulonglong2*)(Bk + bo2);
            ulonglong2 b67 = *(const ulonglong2*)(Bk + bo3);
            uint64_t bd[8] = {b01.x, b01.y, b23.x, b23.y, b45.x, b45.y, b67.x, b67.y};
#pragma unroll
            for (int n = 0; n < 8; ++n) {
                FMA2(acc[0][0][n], aR.x, bd[n]);
                FMA2(acc[0][1][n], aR.y, bd[n]);
                FMA2(acc[1][0][n], aL.x, bd[n]);
                FMA2(acc[1][1][n], aL.y, bd[n]);
                FMA2(acc[2][0][n], aH.x, bd[n]);
                FMA2(acc[2][1][n], aH.y, bd[n]);
            }
        }

        // splitK=2 fold after tiles 63 and 127 (k=2048, 4096)
        if (((t + 1) & 63) == 0) {
#pragma unroll
            for (int m = 0; m < 3; ++m)
#pragma unroll
                for (int p = 0; p < 2; ++p)
#pragma unroll
                    for (int n = 0; n < 8; ++n) {
                        ADD2(run[m][p][n], acc[m][p][n]);
                        acc[m][p][n] = 0ull;
                    }
        }
        stage = (stage + 1) % 3;
    }

    // Epilogue: exact reference combine, vectorized stores.
    float4 bv0 = *(const float4*)(bvec + col0 + (tx << 2));
    float4 bv1 = *(const float4*)(bvec + col0 + 64 + (tx << 2));
    float bj[8] = {bv0.x, bv0.y, bv0.z, bv0.w, bv1.x, bv1.y, bv1.z, bv1.w};

#pragma unroll
    for (int half = 0; half < 2; ++half) {
#pragma unroll
        for (int mm = 0; mm < 4; ++mm) {
            const int i = row0 + (ty << 2) + mm;
            const int mp = mm >> 1, lane = mm & 1;
            float o[4];
#pragma unroll
            for (int q = 0; q < 4; ++q) {
                const int n = half * 4 + q;
                float r0, r1, l0, l1, h0, h1;
                UNPK(r0, r1, run[0][mp][n]);
                UNPK(l0, l1, run[1][mp][n]);
                UNPK(h0, h1, run[2][mp][n]);
                float gR = lane ? r1 : r0;
                float gL = lane ? l1 : l0;
                float gH = lane ? h1 : h0;
                float oL = __fadd_rn(gL, bj[n]);
                double v = __dadd_rn((double)oL, __dmul_rn(2291.0, (double)gH));
                float f = (float)v;
                o[q] = __fmul_rn(__fsub_rn(f, gR), 0.00390625f);
            }
            *(float4*)(out + (long long)i * ND + col0 + half * 64 + (tx << 2)) =
                make_float4(o[0], o[1], o[2], o[3]);
        }
    }
}

extern "C" void kernel_launch(void* const* d_in, const int* in_sizes, int n_in,
                              void* d_out, int out_size) {
    const float* x = (const float*)d_in[0];
    const float* r = (const float*)d_in[1];
    const float* W = (const float*)d_in[2];
    const float* b = (const float*)d_in[3];
    float* out = (float*)d_out;

    dim3 gp(ND / 32, ND / 32);
    prep_T<<<gp, 256>>>(x, r);
    prep_Wd<<<(unsigned)(((size_t)ND * ND / 4) / 256), 256>>>(W);

    cudaFuncSetAttribute(gemm3_dup_kernel,
                         cudaFuncAttributeMaxDynamicSharedMemorySize, SMEM_BYTES);
    dim3 grid(ND / BN, ND / BM);
    gemm3_dup_kernel<<<grid, 256, SMEM_BYTES>>>(b, out);
}

// round 16
// speedup vs baseline: 1.1704x; 1.1704x over previous
#include <cuda_runtime.h>
#include <cstdint>
#include <math.h>

#define ND 4096
#define BM 64
#define BN 128
#define BK 32
#define NT (ND / BK)          // 128 k-tiles; splitK=2 fold after tiles 63,127

#define A_PITCH 68
#define B_PITCH 132
#define A_FLOATS (3 * 32 * A_PITCH)            // 6528
#define STG_FLOATS (A_FLOATS + 32 * B_PITCH)   // 10752
#define SMEM_BYTES (3 * STG_FLOATS * 4)        // 129024

#define NTHREADS 512
#define TOTTH ((size_t)2048 * NTHREADS)        // grid 32x64 = 2048 CTAs

// Scratch (allocation-free): transposed A planes + splitK half sums.
static __device__ float g_rT[(size_t)ND * ND];
static __device__ float g_lowT[(size_t)ND * ND];
static __device__ float g_highT[(size_t)ND * ND];
static __device__ uint64_t g_half[24 * TOTTH];   // 24 f32x2 per thread, 192 MB

// f32x2 packed helpers (per-lane IEEE RN — bit-identical to scalar FFMA/FADD)
#define FMA2(acc, a, b) asm("fma.rn.f32x2 %0, %1, %2, %0;" : "+l"(acc) : "l"(a), "l"(b))
#define ADD2(acc, v)    asm("add.rn.f32x2 %0, %0, %1;" : "+l"(acc) : "l"(v))
#define DUP2(d, s)      asm("mov.b64 %0, {%1, %1};" : "=l"(d) : "f"(s))
#define UNPK(lo, hi, v) asm("mov.b64 {%0, %1}, %2;" : "=f"(lo), "=f"(hi) : "l"(v))

#define CP16(dst, src) \
    asm volatile("cp.async.cg.shared.global [%0], [%1], 16;" :: "r"(dst), "l"(src))

__device__ __forceinline__ uint32_t smem_u32(const void* p) {
    uint32_t a;
    asm("{ .reg .u64 t; cvta.to.shared.u64 t, %1; cvt.u32.u64 %0, t; }" : "=r"(a) : "l"(p));
    return a;
}

// Digit split (exact jnp semantics, bit-exact since R10) + 32x32 transpose.
__global__ void __launch_bounds__(256) prep_T(const float* __restrict__ x,
                                              const float* __restrict__ r) {
    __shared__ float tR[32][33], tL[32][33], tH[32][33];
    const int tx = threadIdx.x & 31, ty = threadIdx.x >> 5;
    const int m0 = blockIdx.x * 32, k0 = blockIdx.y * 32;
#pragma unroll
    for (int i = 0; i < 4; ++i) {
        const int ml = ty + 8 * i;
        const size_t idx = (size_t)(m0 + ml) * ND + k0 + tx;
        float rv = r[idx];
        float xb = __fadd_rn(x[idx], rv);
        float low = fmodf(xb, 2291.0f);
        if (low < 0.0f) low = __fadd_rn(low, 2291.0f);
        float high = rintf(__fdiv_rn(__fsub_rn(xb, low), 2291.0f));
        tR[ml][tx] = rv;
        tL[ml][tx] = low;
        tH[ml][tx] = high;
    }
    __syncthreads();
#pragma unroll
    for (int i = 0; i < 4; ++i) {
        const int kl = ty + 8 * i;
        const size_t o = (size_t)(k0 + kl) * ND + m0 + tx;
        g_rT[o]    = tR[tx][kl];
        g_lowT[o]  = tL[tx][kl];
        g_highT[o] = tH[tx][kl];
    }
}

// Fused triple-SGEMM, splitK=2 rounding (bit-exact), f32x2 math, 3-stage
// cp.async pipeline (race-free ordering), 512 threads @ ~90 regs -> 25% occ.
// First-half sums parked in global scratch to halve the accumulator RF.
__global__ void __launch_bounds__(NTHREADS, 1) gemm3_occ_kernel(
        const float* __restrict__ W,
        const float* __restrict__ bvec,
        float* __restrict__ out) {
    extern __shared__ __align__(16) float smem[];

    const int tid  = threadIdx.x;
    const int tx   = tid & 31;        // n group: cols 4tx..4tx+3
    const int ty   = tid >> 5;        // m group: rows 4ty..4ty+3
    const int row0 = blockIdx.y * BM;
    const int col0 = blockIdx.x * BN;
    const size_t gtid = ((size_t)blockIdx.y * 32 + blockIdx.x) * NTHREADS + tid;

    const uint32_t sbase = smem_u32(smem);
    const float* srcA[3] = {g_rT, g_lowT, g_highT};

    // acc[mat][mpair][n]: f32x2 lanes = (m=4ty+2mp, m=4ty+2mp+1)
    uint64_t acc[3][2][4];
#pragma unroll
    for (int m = 0; m < 3; ++m)
#pragma unroll
        for (int p = 0; p < 2; ++p)
#pragma unroll
            for (int n = 0; n < 4; ++n) acc[m][p][n] = 0ull;

    // Loader: A = 1536 chunks (3/thread), B = 1024 chunks (2/thread)
#define LOAD_TILE(t, stg)                                                          \
    do {                                                                           \
        const int _k0 = (t) * BK;                                                  \
        const uint32_t _sb = sbase + (uint32_t)(stg) * (STG_FLOATS * 4);           \
        _Pragma("unroll")                                                          \
        for (int _i = 0; _i < 3; ++_i) {                                           \
            const int _lin = _i * NTHREADS + tid;                                  \
            const int _pl = _lin >> 9, _kr = (_lin >> 4) & 31, _q = _lin & 15;     \
            const float* _s = srcA[_pl] + (size_t)(_k0 + _kr) * ND + row0 + _q * 4;\
            CP16(_sb + (uint32_t)((_pl * 32 + _kr) * (A_PITCH * 4) + _q * 16), _s);\
        }                                                                          \
        _Pragma("unroll")                                                          \
        for (int _i = 0; _i < 2; ++_i) {                                           \
            const int _lin = _i * NTHREADS + tid;                                  \
            const int _kr = _lin >> 5, _q = _lin & 31;                             \
            const float* _s = W + (size_t)(_k0 + _kr) * ND + col0 + _q * 4;        \
            CP16(_sb + (uint32_t)(A_FLOATS * 4 + _kr * (B_PITCH * 4) + _q * 16), _s); \
        }                                                                          \
    } while (0)

    LOAD_TILE(0, 0);
    asm volatile("cp.async.commit_group;" ::: "memory");
    LOAD_TILE(1, 1);
    asm volatile("cp.async.commit_group;" ::: "memory");

    int stage = 0;
    for (int t = 0; t < NT; ++t) {
        asm volatile("cp.async.wait_group 1;" ::: "memory");
        __syncthreads();
        if (t + 2 < NT) LOAD_TILE(t + 2, (stage + 2) % 3);
        asm volatile("cp.async.commit_group;" ::: "memory");

        const float* As = smem + stage * STG_FLOATS;
        const float* Bs = As + A_FLOATS;

#pragma unroll
        for (int k = 0; k < BK; ++k) {
            ulonglong2 aR = *(const ulonglong2*)(As + (0 * 32 + k) * A_PITCH + (ty << 2));
            ulonglong2 aL = *(const ulonglong2*)(As + (1 * 32 + k) * A_PITCH + (ty << 2));
            ulonglong2 aH = *(const ulonglong2*)(As + (2 * 32 + k) * A_PITCH + (ty << 2));
            float4 b0 = *(const float4*)(Bs + k * B_PITCH + (tx << 2));
            uint64_t bd[4];
            DUP2(bd[0], b0.x); DUP2(bd[1], b0.y); DUP2(bd[2], b0.z); DUP2(bd[3], b0.w);
#pragma unroll
            for (int n = 0; n < 4; ++n) {
                FMA2(acc[0][0][n], aR.x, bd[n]);
                FMA2(acc[0][1][n], aR.y, bd[n]);
                FMA2(acc[1][0][n], aL.x, bd[n]);
                FMA2(acc[1][1][n], aL.y, bd[n]);
                FMA2(acc[2][0][n], aH.x, bd[n]);
                FMA2(acc[2][1][n], aH.y, bd[n]);
            }
        }

        // splitK=2: after tile 63 (k=2048), park first-half sums in global
        // scratch (coalesced planes) and restart the chain.
        if (t == 63) {
#pragma unroll
            for (int m = 0; m < 3; ++m)
#pragma unroll
                for (int p = 0; p < 2; ++p)
#pragma unroll
                    for (int n = 0; n < 4; ++n) {
                        const int s = (m * 2 + p) * 4 + n;
                        g_half[(size_t)s * TOTTH + gtid] = acc[m][p][n];
                        acc[m][p][n] = 0ull;
                    }
        }
        stage = (stage + 1) % 3;
    }

    // Epilogue: fold halves (RN add, commutative == reference chain0+chain1),
    // then the exact reference combine; vectorized stores.
    float4 bv = *(const float4*)(bvec + col0 + (tx << 2));
    float bj[4] = {bv.x, bv.y, bv.z, bv.w};

    uint64_t tot[3][2][4];
#pragma unroll
    for (int m = 0; m < 3; ++m)
#pragma unroll
        for (int p = 0; p < 2; ++p)
#pragma unroll
            for (int n = 0; n < 4; ++n) {
                const int s = (m * 2 + p) * 4 + n;
                uint64_t h = g_half[(size_t)s * TOTTH + gtid];
                ADD2(h, acc[m][p][n]);
                tot[m][p][n] = h;
            }

#pragma unroll
    for (int mm = 0; mm < 4; ++mm) {
        const int i = row0 + (ty << 2) + mm;
        const int mp = mm >> 1, lane = mm & 1;
        float o[4];
#pragma unroll
        for (int n = 0; n < 4; ++n) {
            float r0, r1, l0, l1, h0, h1;
            UNPK(r0, r1, tot[0][mp][n]);
            UNPK(l0, l1, tot[1][mp][n]);
            UNPK(h0, h1, tot[2][mp][n]);
            float gR = lane ? r1 : r0;
            float gL = lane ? l1 : l0;
            float gH = lane ? h1 : h0;
            float oL = __fadd_rn(gL, bj[n]);
            double v = __dadd_rn((double)oL, __dmul_rn(2291.0, (double)gH));
            float f = (float)v;
            o[n] = __fmul_rn(__fsub_rn(f, gR), 0.00390625f);
        }
        *(float4*)(out + (long long)i * ND + col0 + (tx << 2)) =
            make_float4(o[0], o[1], o[2], o[3]);
    }
}

extern "C" void kernel_launch(void* const* d_in, const int* in_sizes, int n_in,
                              void* d_out, int out_size) {
    const float* x = (const float*)d_in[0];
    const float* r = (const float*)d_in[1];
    const float* W = (const float*)d_in[2];
    const float* b = (const float*)d_in[3];
    float* out = (float*)d_out;

    dim3 gp(ND / 32, ND / 32);
    prep_T<<<gp, 256>>>(x, r);

    cudaFuncSetAttribute(gemm3_occ_kernel,
                         cudaFuncAttributeMaxDynamicSharedMemorySize, SMEM_BYTES);
    dim3 grid(ND / BN, ND / BM);
    gemm3_occ_kernel<<<grid, NTHREADS, SMEM_BYTES>>>(W, b, out);
}

// round 17
// speedup vs baseline: 1.1754x; 1.0043x over previous
#include <cuda_runtime.h>
#include <cstdint>
#include <math.h>

#define ND 4096
#define BM 64
#define BN 64
#define BK 32
#define NT (ND / BK)          // 128 k-tiles; splitK=2 park after tile 63

#define A_PITCH 68
#define B_PITCH 68
#define A_FLOATS (3 * 32 * A_PITCH)            // 6528
#define STG_FLOATS (A_FLOATS + 32 * B_PITCH)   // 8704
#define SMEM_BYTES (3 * STG_FLOATS * 4)        // 104448 -> 2 CTAs/SM

#define NTHREADS 256
#define NBLK (64 * 64)                          // 4096 CTAs
#define TOTTH ((size_t)NBLK * NTHREADS)

// Scratch (allocation-free): transposed A planes + splitK half sums.
static __device__ float g_rT[(size_t)ND * ND];
static __device__ float g_lowT[(size_t)ND * ND];
static __device__ float g_highT[(size_t)ND * ND];
static __device__ uint64_t g_half[24 * TOTTH];

// f32x2 packed helpers (per-lane IEEE RN — bit-identical to scalar FFMA/FADD)
#define FMA2(acc, a, b) asm("fma.rn.f32x2 %0, %1, %2, %0;" : "+l"(acc) : "l"(a), "l"(b))
#define ADD2(acc, v)    asm("add.rn.f32x2 %0, %0, %1;" : "+l"(acc) : "l"(v))
#define DUP2(d, s)      asm("mov.b64 %0, {%1, %1};" : "=l"(d) : "f"(s))
#define UNPK(lo, hi, v) asm("mov.b64 {%0, %1}, %2;" : "=f"(lo), "=f"(hi) : "l"(v))

#define CP16(dst, src) \
    asm volatile("cp.async.cg.shared.global [%0], [%1], 16;" :: "r"(dst), "l"(src))

__device__ __forceinline__ uint32_t smem_u32(const void* p) {
    uint32_t a;
    asm("{ .reg .u64 t; cvta.to.shared.u64 t, %1; cvt.u32.u64 %0, t; }" : "=r"(a) : "l"(p));
    return a;
}

// Digit split (exact jnp semantics, bit-exact since R10) + 32x32 transpose.
__global__ void __launch_bounds__(256) prep_T(const float* __restrict__ x,
                                              const float* __restrict__ r) {
    __shared__ float tR[32][33], tL[32][33], tH[32][33];
    const int tx = threadIdx.x & 31, ty = threadIdx.x >> 5;
    const int m0 = blockIdx.x * 32, k0 = blockIdx.y * 32;
#pragma unroll
    for (int i = 0; i < 4; ++i) {
        const int ml = ty + 8 * i;
        const size_t idx = (size_t)(m0 + ml) * ND + k0 + tx;
        float rv = r[idx];
        float xb = __fadd_rn(x[idx], rv);
        float low = fmodf(xb, 2291.0f);
        if (low < 0.0f) low = __fadd_rn(low, 2291.0f);
        float high = rintf(__fdiv_rn(__fsub_rn(xb, low), 2291.0f));
        tR[ml][tx] = rv;
        tL[ml][tx] = low;
        tH[ml][tx] = high;
    }
    __syncthreads();
#pragma unroll
    for (int i = 0; i < 4; ++i) {
        const int kl = ty + 8 * i;
        const size_t o = (size_t)(k0 + kl) * ND + m0 + tx;
        g_rT[o]    = tR[tx][kl];
        g_lowT[o]  = tL[tx][kl];
        g_highT[o] = tH[tx][kl];
    }
}

// Fused triple-SGEMM, splitK=2 rounding (bit-exact), f32x2 math, 3-stage
// cp.async pipeline (race-free ordering). 256-thread CTAs, 2 CTAs/SM so one
// CTA's barrier bubbles overlap the other's FMA work.
__global__ void __launch_bounds__(NTHREADS, 2) gemm3_2cta_kernel(
        const float* __restrict__ W,
        const float* __restrict__ bvec,
        float* __restrict__ out) {
    extern __shared__ __align__(16) float smem[];

    const int tid  = threadIdx.x;
    const int tx   = tid & 15;        // n group: cols 4tx..4tx+3
    const int ty   = tid >> 4;        // m group: rows 4ty..4ty+3
    const int row0 = blockIdx.y * BM;
    const int col0 = blockIdx.x * BN;
    const size_t gtid = ((size_t)blockIdx.y * 64 + blockIdx.x) * NTHREADS + tid;

    const uint32_t sbase = smem_u32(smem);
    const float* srcA[3] = {g_rT, g_lowT, g_highT};

    uint64_t acc[3][2][4];
#pragma unroll
    for (int m = 0; m < 3; ++m)
#pragma unroll
        for (int p = 0; p < 2; ++p)
#pragma unroll
            for (int n = 0; n < 4; ++n) acc[m][p][n] = 0ull;

    // Loader: A = 1536 16B-chunks (6/thread), B = 512 chunks (2/thread)
#define LOAD_TILE(t, stg)                                                          \
    do {                                                                           \
        const int _k0 = (t) * BK;                                                  \
        const uint32_t _sb = sbase + (uint32_t)(stg) * (STG_FLOATS * 4);           \
        _Pragma("unroll")                                                          \
        for (int _i = 0; _i < 6; ++_i) {                                           \
            const int _lin = _i * NTHREADS + tid;                                  \
            const int _pl = _lin >> 9, _kr = (_lin >> 4) & 31, _q = _lin & 15;     \
            const float* _s = srcA[_pl] + (size_t)(_k0 + _kr) * ND + row0 + _q * 4;\
            CP16(_sb + (uint32_t)((_pl * 32 + _kr) * (A_PITCH * 4) + _q * 16), _s);\
        }                                                                          \
        _Pragma("unroll")                                                          \
        for (int _i = 0; _i < 2; ++_i) {                                           \
            const int _lin = _i * NTHREADS + tid;                                  \
            const int _kr = _lin >> 4, _q = _lin & 15;                             \
            const float* _s = W + (size_t)(_k0 + _kr) * ND + col0 + _q * 4;        \
            CP16(_sb + (uint32_t)(A_FLOATS * 4 + _kr * (B_PITCH * 4) + _q * 16), _s); \
        }                                                                          \
    } while (0)

    LOAD_TILE(0, 0);
    asm volatile("cp.async.commit_group;" ::: "memory");
    LOAD_TILE(1, 1);
    asm volatile("cp.async.commit_group;" ::: "memory");

    int stage = 0;
    for (int t = 0; t < NT; ++t) {
        asm volatile("cp.async.wait_group 1;" ::: "memory");
        __syncthreads();
        if (t + 2 < NT) LOAD_TILE(t + 2, (stage + 2) % 3);
        asm volatile("cp.async.commit_group;" ::: "memory");

        const float* As = smem + stage * STG_FLOATS;
        const float* Bs = As + A_FLOATS;

#pragma unroll
        for (int k = 0; k < BK; ++k) {
            ulonglong2 aR = *(const ulonglong2*)(As + (0 * 32 + k) * A_PITCH + (ty << 2));
            ulonglong2 aL = *(const ulonglong2*)(As + (1 * 32 + k) * A_PITCH + (ty << 2));
            ulonglong2 aH = *(const ulonglong2*)(As + (2 * 32 + k) * A_PITCH + (ty << 2));
            float4 b0 = *(const float4*)(Bs + k * B_PITCH + (tx << 2));
            uint64_t bd[4];
            DUP2(bd[0], b0.x); DUP2(bd[1], b0.y); DUP2(bd[2], b0.z); DUP2(bd[3], b0.w);
#pragma unroll
            for (int n = 0; n < 4; ++n) {
                FMA2(acc[0][0][n], aR.x, bd[n]);
                FMA2(acc[0][1][n], aR.y, bd[n]);
                FMA2(acc[1][0][n], aL.x, bd[n]);
                FMA2(acc[1][1][n], aL.y, bd[n]);
                FMA2(acc[2][0][n], aH.x, bd[n]);
                FMA2(acc[2][1][n], aH.y, bd[n]);
            }
        }

        // splitK=2: after tile 63 (k=2048), park first-half sums.
        if (t == 63) {
#pragma unroll
            for (int m = 0; m < 3; ++m)
#pragma unroll
                for (int p = 0; p < 2; ++p)
#pragma unroll
                    for (int n = 0; n < 4; ++n) {
                        const int s = (m * 2 + p) * 4 + n;
                        g_half[(size_t)s * TOTTH + gtid] = acc[m][p][n];
                        acc[m][p][n] = 0ull;
                    }
        }
        stage = (stage + 1) % 3;
    }

    // Epilogue: fold halves (RN add == reference chain0+chain1), exact combine.
    float4 bv = *(const float4*)(bvec + col0 + (tx << 2));
    float bj[4] = {bv.x, bv.y, bv.z, bv.w};

    uint64_t tot[3][2][4];
#pragma unroll
    for (int m = 0; m < 3; ++m)
#pragma unroll
        for (int p = 0; p < 2; ++p)
#pragma unroll
            for (int n = 0; n < 4; ++n) {
                const int s = (m * 2 + p) * 4 + n;
                uint64_t h = g_half[(size_t)s * TOTTH + gtid];
                ADD2(h, acc[m][p][n]);
                tot[m][p][n] = h;
            }

#pragma unroll
    for (int mm = 0; mm < 4; ++mm) {
        const int i = row0 + (ty << 2) + mm;
        const int mp = mm >> 1, lane = mm & 1;
        float o[4];
#pragma unroll
        for (int n = 0; n < 4; ++n) {
            float r0, r1, l0, l1, h0, h1;
            UNPK(r0, r1, tot[0][mp][n]);
            UNPK(l0, l1, tot[1][mp][n]);
            UNPK(h0, h1, tot[2][mp][n]);
            float gR = lane ? r1 : r0;
            float gL = lane ? l1 : l0;
            float gH = lane ? h1 : h0;
            float oL = __fadd_rn(gL, bj[n]);
            double v = __dadd_rn((double)oL, __dmul_rn(2291.0, (double)gH));
            float f = (float)v;
            o[n] = __fmul_rn(__fsub_rn(f, gR), 0.00390625f);
        }
        *(float4*)(out + (long long)i * ND + col0 + (tx << 2)) =
            make_float4(o[0], o[1], o[2], o[3]);
    }
}

extern "C" void kernel_launch(void* const* d_in, const int* in_sizes, int n_in,
                              void* d_out, int out_size) {
    const float* x = (const float*)d_in[0];
    const float* r = (const float*)d_in[1];
    const float* W = (const float*)d_in[2];
    const float* b = (const float*)d_in[3];
    float* out = (float*)d_out;

    dim3 gp(ND / 32, ND / 32);
    prep_T<<<gp, 256>>>(x, r);

    cudaFuncSetAttribute(gemm3_2cta_kernel,
                         cudaFuncAttributeMaxDynamicSharedMemorySize, SMEM_BYTES);
    dim3 grid(ND / BN, ND / BM);
    gemm3_2cta_kernel<<<grid, NTHREADS, SMEM_BYTES>>>(W, b, out);
}